// round 2
// baseline (speedup 1.0000x reference)
#include <cuda_runtime.h>
#include <math.h>

// Problem constants
#define BB 2
#define TT 2048
#define HH 16
#define DD 64
#define CC 1024
#define MM (BB*TT)   // 4096

// Scratch (allocation-free rule: __device__ globals)
__device__ float g_q[MM*CC];
__device__ float g_k[MM*CC];
__device__ float g_v[MM*CC];
__device__ float g_att[MM*CC];

// ---------------------------------------------------------------------------
// SGEMM: out[m,n] = sum_k A[m,k] * W[n,k] + bias[n]
// M=4096, N=1024, K=1024. BM=BN=128, BK=16, 256 threads, 8x8 microtile,
// double-buffered smem, padded to reduce STS bank conflicts.
// ---------------------------------------------------------------------------
#define BMg 128
#define BNg 128
#define BKg 16
#define PADg 4

__device__ __forceinline__ void sgemm_body(
    const float* __restrict__ A, const float* __restrict__ W,
    const float* __restrict__ bias, float* __restrict__ out)
{
    const int K = 1024, N = 1024;
    __shared__ float As[2][BKg][BMg + PADg];
    __shared__ float Bs[2][BKg][BNg + PADg];

    int tid = threadIdx.x;
    int tx = tid & 15;        // 0..15 -> output cols (8 each)
    int ty = tid >> 4;        // 0..15 -> output rows (8 each)
    int m0 = blockIdx.y * BMg;
    int n0 = blockIdx.x * BNg;

    // loader mapping: 256 threads cover 128 rows x 16 cols in 2 float4 each
    int ar = tid >> 2;          // 0..63
    int ac = (tid & 3) * 4;     // 0,4,8,12

    const float* Aptr0 = A + (size_t)(m0 + ar) * K + ac;
    const float* Aptr1 = A + (size_t)(m0 + ar + 64) * K + ac;
    const float* Wptr0 = W + (size_t)(n0 + ar) * K + ac;
    const float* Wptr1 = W + (size_t)(n0 + ar + 64) * K + ac;

    float acc[8][8];
#pragma unroll
    for (int i = 0; i < 8; i++)
#pragma unroll
        for (int j = 0; j < 8; j++) acc[i][j] = 0.f;

    // prefetch tile 0
    float4 a0 = *(const float4*)(Aptr0);
    float4 a1 = *(const float4*)(Aptr1);
    float4 w0 = *(const float4*)(Wptr0);
    float4 w1 = *(const float4*)(Wptr1);
    {
        As[0][ac+0][ar] = a0.x; As[0][ac+1][ar] = a0.y;
        As[0][ac+2][ar] = a0.z; As[0][ac+3][ar] = a0.w;
        As[0][ac+0][ar+64] = a1.x; As[0][ac+1][ar+64] = a1.y;
        As[0][ac+2][ar+64] = a1.z; As[0][ac+3][ar+64] = a1.w;
        Bs[0][ac+0][ar] = w0.x; Bs[0][ac+1][ar] = w0.y;
        Bs[0][ac+2][ar] = w0.z; Bs[0][ac+3][ar] = w0.w;
        Bs[0][ac+0][ar+64] = w1.x; Bs[0][ac+1][ar+64] = w1.y;
        Bs[0][ac+2][ar+64] = w1.z; Bs[0][ac+3][ar+64] = w1.w;
    }
    __syncthreads();

    int buf = 0;
    const int NT = K / BKg;    // 64
    for (int it = 1; it < NT; it++) {
        int k0 = it * BKg;
        // prefetch next tile into regs
        a0 = *(const float4*)(Aptr0 + k0);
        a1 = *(const float4*)(Aptr1 + k0);
        w0 = *(const float4*)(Wptr0 + k0);
        w1 = *(const float4*)(Wptr1 + k0);

        // compute on current buffer
#pragma unroll
        for (int kk = 0; kk < BKg; kk++) {
            float4 av0 = *(const float4*)&As[buf][kk][ty*8];
            float4 av1 = *(const float4*)&As[buf][kk][ty*8+4];
            float4 bv0 = *(const float4*)&Bs[buf][kk][tx*8];
            float4 bv1 = *(const float4*)&Bs[buf][kk][tx*8+4];
            float af[8] = {av0.x,av0.y,av0.z,av0.w,av1.x,av1.y,av1.z,av1.w};
            float bf[8] = {bv0.x,bv0.y,bv0.z,bv0.w,bv1.x,bv1.y,bv1.z,bv1.w};
#pragma unroll
            for (int i = 0; i < 8; i++)
#pragma unroll
                for (int j = 0; j < 8; j++)
                    acc[i][j] += af[i] * bf[j];
        }

        // store prefetched tile into other buffer
        int nb = buf ^ 1;
        As[nb][ac+0][ar] = a0.x; As[nb][ac+1][ar] = a0.y;
        As[nb][ac+2][ar] = a0.z; As[nb][ac+3][ar] = a0.w;
        As[nb][ac+0][ar+64] = a1.x; As[nb][ac+1][ar+64] = a1.y;
        As[nb][ac+2][ar+64] = a1.z; As[nb][ac+3][ar+64] = a1.w;
        Bs[nb][ac+0][ar] = w0.x; Bs[nb][ac+1][ar] = w0.y;
        Bs[nb][ac+2][ar] = w0.z; Bs[nb][ac+3][ar] = w0.w;
        Bs[nb][ac+0][ar+64] = w1.x; Bs[nb][ac+1][ar+64] = w1.y;
        Bs[nb][ac+2][ar+64] = w1.z; Bs[nb][ac+3][ar+64] = w1.w;
        __syncthreads();
        buf = nb;
    }

    // last tile
#pragma unroll
    for (int kk = 0; kk < BKg; kk++) {
        float4 av0 = *(const float4*)&As[buf][kk][ty*8];
        float4 av1 = *(const float4*)&As[buf][kk][ty*8+4];
        float4 bv0 = *(const float4*)&Bs[buf][kk][tx*8];
        float4 bv1 = *(const float4*)&Bs[buf][kk][tx*8+4];
        float af[8] = {av0.x,av0.y,av0.z,av0.w,av1.x,av1.y,av1.z,av1.w};
        float bf[8] = {bv0.x,bv0.y,bv0.z,bv0.w,bv1.x,bv1.y,bv1.z,bv1.w};
#pragma unroll
        for (int i = 0; i < 8; i++)
#pragma unroll
            for (int j = 0; j < 8; j++)
                acc[i][j] += af[i] * bf[j];
    }

    float bb[8];
#pragma unroll
    for (int j = 0; j < 8; j++) bb[j] = bias[n0 + tx*8 + j];

#pragma unroll
    for (int i = 0; i < 8; i++) {
        int row = m0 + ty*8 + i;
        float* orow = out + (size_t)row * N + n0 + tx*8;
        float4 r0, r1;
        r0.x = acc[i][0] + bb[0]; r0.y = acc[i][1] + bb[1];
        r0.z = acc[i][2] + bb[2]; r0.w = acc[i][3] + bb[3];
        r1.x = acc[i][4] + bb[4]; r1.y = acc[i][5] + bb[5];
        r1.z = acc[i][6] + bb[6]; r1.w = acc[i][7] + bb[7];
        *(float4*)(orow)     = r0;
        *(float4*)(orow + 4) = r1;
    }
}

__global__ __launch_bounds__(256)
void sgemm_qkv_kernel(const float* __restrict__ x,
                      const float* __restrict__ Wq, const float* __restrict__ bq,
                      const float* __restrict__ Wk, const float* __restrict__ bk,
                      const float* __restrict__ Wv, const float* __restrict__ bv)
{
    const float* W; const float* b; float* out;
    if (blockIdx.z == 0)      { W = Wq; b = bq; out = g_q; }
    else if (blockIdx.z == 1) { W = Wk; b = bk; out = g_k; }
    else                      { W = Wv; b = bv; out = g_v; }
    sgemm_body(x, W, b, out);
}

__global__ __launch_bounds__(256)
void sgemm_proj_kernel(const float* __restrict__ Wp, const float* __restrict__ bp,
                       float* __restrict__ out)
{
    sgemm_body(g_att, Wp, bp, out);
}

// ---------------------------------------------------------------------------
// RoPE in-place on g_q, g_k. Layout [B,T,H,D].
// ---------------------------------------------------------------------------
#define NPAIR (BB*TT*HH*32)

__global__ __launch_bounds__(256)
void rope_kernel()
{
    int idx = blockIdx.x * blockDim.x + threadIdx.x;
    if (idx >= 2 * NPAIR) return;
    float* arr = (idx < NPAIR) ? g_q : g_k;
    int i = (idx < NPAIR) ? idx : idx - NPAIR;
    int j = i & 31;
    int h = (i >> 5) & 15;
    int t = (i >> 9) & 2047;
    int b = i >> 20;
    const float L = 13.287712379549449f / 32.0f;  // log2(10000)/32
    float inv = exp2f(-(float)j * L);
    float ang = (float)t * inv;
    float c, s;
    sincosf(ang, &s, &c);
    float* p = arr + (((size_t)(b*TT + t))*HH + h) * DD;
    float x1 = p[j];
    float x2 = p[j + 32];
    p[j]      = x1 * c - x2 * s;
    p[j + 32] = x2 * c + x1 * s;
}

// ---------------------------------------------------------------------------
// Causal flash attention, fp32. 1 thread per query row, 128 rows/block.
// Keys processed in chunks of 16: independent dots (4 partial accumulators
// each), one online-softmax rescale per chunk. Mask with -1e30 sentinel.
// ---------------------------------------------------------------------------
__global__ __launch_bounds__(128)
void attn_kernel()
{
    __shared__ float Ks[64][64];
    __shared__ float Vs[64][64];

    int tid = threadIdx.x;
    int bh = blockIdx.y;
    int b = bh >> 4, h = bh & 15;
    int t = blockIdx.x * 128 + tid;

    const float* qrow = g_q + (((size_t)(b*TT + t))*HH + h) * DD;
    float qreg[64];
#pragma unroll
    for (int i = 0; i < 16; i++) {
        float4 v4 = ((const float4*)qrow)[i];
        qreg[4*i]   = v4.x; qreg[4*i+1] = v4.y;
        qreg[4*i+2] = v4.z; qreg[4*i+3] = v4.w;
    }

    float mx = -1e30f, l = 0.f;
    float acc[64];
#pragma unroll
    for (int d = 0; d < 64; d++) acc[d] = 0.f;

    int t_last = blockIdx.x * 128 + 127;

    for (int n0 = 0; n0 <= t_last; n0 += 64) {
        const float4* kbase = (const float4*)(g_k + (((size_t)(b*TT + n0))*HH + h) * DD);
        const float4* vbase = (const float4*)(g_v + (((size_t)(b*TT + n0))*HH + h) * DD);
#pragma unroll
        for (int i = 0; i < 8; i++) {
            int idx = tid + i * 128;
            int kr = idx >> 4;
            int d4 = idx & 15;
            ((float4*)&Ks[kr][0])[d4] = kbase[(size_t)kr * (HH*DD/4) + d4];
            ((float4*)&Vs[kr][0])[d4] = vbase[(size_t)kr * (HH*DD/4) + d4];
        }
        __syncthreads();

        int rel = t - n0;   // last valid key index in this tile (may be <0..63+)

        for (int j0 = 0; j0 < 64; j0 += 16) {
            if (rel < j0) break;   // this chunk (and later ones) fully masked

            float s[16];
#pragma unroll
            for (int jj = 0; jj < 16; jj++) {
                const float4* kr4 = (const float4*)&Ks[j0 + jj][0];
                float p0 = 0.f, p1 = 0.f, p2 = 0.f, p3 = 0.f;
#pragma unroll
                for (int d4 = 0; d4 < 16; d4 += 4) {
                    float4 k0 = kr4[d4+0];
                    float4 k1 = kr4[d4+1];
                    float4 k2 = kr4[d4+2];
                    float4 k3 = kr4[d4+3];
                    p0 += qreg[4*(d4+0)]*k0.x + qreg[4*(d4+0)+1]*k0.y
                        + qreg[4*(d4+0)+2]*k0.z + qreg[4*(d4+0)+3]*k0.w;
                    p1 += qreg[4*(d4+1)]*k1.x + qreg[4*(d4+1)+1]*k1.y
                        + qreg[4*(d4+1)+2]*k1.z + qreg[4*(d4+1)+3]*k1.w;
                    p2 += qreg[4*(d4+2)]*k2.x + qreg[4*(d4+2)+1]*k2.y
                        + qreg[4*(d4+2)+2]*k2.z + qreg[4*(d4+2)+3]*k2.w;
                    p3 += qreg[4*(d4+3)]*k3.x + qreg[4*(d4+3)+1]*k3.y
                        + qreg[4*(d4+3)+2]*k3.z + qreg[4*(d4+3)+3]*k3.w;
                }
                s[jj] = ((p0 + p1) + (p2 + p3)) * 0.125f;
            }

            // causal mask within chunk
#pragma unroll
            for (int jj = 0; jj < 16; jj++)
                if (j0 + jj > rel) s[jj] = -1e30f;

            // chunk max (tree)
            float m0v = fmaxf(fmaxf(s[0], s[1]),  fmaxf(s[2], s[3]));
            float m1v = fmaxf(fmaxf(s[4], s[5]),  fmaxf(s[6], s[7]));
            float m2v = fmaxf(fmaxf(s[8], s[9]),  fmaxf(s[10], s[11]));
            float m3v = fmaxf(fmaxf(s[12], s[13]), fmaxf(s[14], s[15]));
            float cmax = fmaxf(fmaxf(m0v, m1v), fmaxf(m2v, m3v));

            float nmx = fmaxf(mx, cmax);
            float corr = __expf(mx - nmx);
            mx = nmx;
            l *= corr;
#pragma unroll
            for (int d = 0; d < 64; d++) acc[d] *= corr;

#pragma unroll
            for (int jj = 0; jj < 16; jj++) {
                s[jj] = __expf(s[jj] - nmx);
                l += s[jj];
            }

            // PV accumulate
#pragma unroll
            for (int jj = 0; jj < 16; jj++) {
                float p = s[jj];
                const float4* vr4 = (const float4*)&Vs[j0 + jj][0];
#pragma unroll
                for (int d4 = 0; d4 < 16; d4++) {
                    float4 vv = vr4[d4];
                    acc[4*d4]   += p * vv.x;
                    acc[4*d4+1] += p * vv.y;
                    acc[4*d4+2] += p * vv.z;
                    acc[4*d4+3] += p * vv.w;
                }
            }
        }
        __syncthreads();
    }

    float invl = 1.f / l;
    float* yrow = g_att + ((size_t)(b*TT + t))*CC + h*DD;
#pragma unroll
    for (int d4 = 0; d4 < 16; d4++) {
        float4 o;
        o.x = acc[4*d4]   * invl;
        o.y = acc[4*d4+1] * invl;
        o.z = acc[4*d4+2] * invl;
        o.w = acc[4*d4+3] * invl;
        ((float4*)yrow)[d4] = o;
    }
}

// ---------------------------------------------------------------------------
extern "C" void kernel_launch(void* const* d_in, const int* in_sizes, int n_in,
                              void* d_out, int out_size)
{
    const float* x  = (const float*)d_in[0];
    const float* Wq = (const float*)d_in[1];
    const float* bq = (const float*)d_in[2];
    const float* Wk = (const float*)d_in[3];
    const float* bk = (const float*)d_in[4];
    const float* Wv = (const float*)d_in[5];
    const float* bv = (const float*)d_in[6];
    const float* Wp = (const float*)d_in[7];
    const float* bp = (const float*)d_in[8];
    float* out = (float*)d_out;

    dim3 gemm_grid(1024/128, 4096/128, 3);
    sgemm_qkv_kernel<<<gemm_grid, 256>>>(x, Wq, bq, Wk, bk, Wv, bv);

    int rope_threads = 2 * NPAIR;
    rope_kernel<<<(rope_threads + 255) / 256, 256>>>();

    dim3 attn_grid(TT/128, BB*HH);
    attn_kernel<<<attn_grid, 128>>>();

    dim3 proj_grid(1024/128, 4096/128);
    sgemm_proj_kernel<<<proj_grid, 256>>>(Wp, bp, out);
}

// round 3
// speedup vs baseline: 1.1048x; 1.1048x over previous
#include <cuda_runtime.h>
#include <math.h>

// Problem constants
#define BB 2
#define TT 2048
#define HH 16
#define DD 64
#define CC 1024
#define MM (BB*TT)   // 4096

// Scratch (allocation-free rule: __device__ globals)
__device__ float g_q[MM*CC];
__device__ float g_k[MM*CC];
__device__ float g_v[MM*CC];
__device__ float g_att[MM*CC];

// ---------------------------------------------------------------------------
// SGEMM: out[m,n] = sum_k A[m,k] * W[n,k] + bias[n]
// M=4096, N=1024, K=1024. BM=BN=128, BK=16, 256 threads, 8x8 microtile,
// double-buffered smem. (Unchanged from R2 — confirmed improvement.)
// ---------------------------------------------------------------------------
#define BMg 128
#define BNg 128
#define BKg 16
#define PADg 4

__device__ __forceinline__ void sgemm_body(
    const float* __restrict__ A, const float* __restrict__ W,
    const float* __restrict__ bias, float* __restrict__ out)
{
    const int K = 1024, N = 1024;
    __shared__ float As[2][BKg][BMg + PADg];
    __shared__ float Bs[2][BKg][BNg + PADg];

    int tid = threadIdx.x;
    int tx = tid & 15;
    int ty = tid >> 4;
    int m0 = blockIdx.y * BMg;
    int n0 = blockIdx.x * BNg;

    int ar = tid >> 2;
    int ac = (tid & 3) * 4;

    const float* Aptr0 = A + (size_t)(m0 + ar) * K + ac;
    const float* Aptr1 = A + (size_t)(m0 + ar + 64) * K + ac;
    const float* Wptr0 = W + (size_t)(n0 + ar) * K + ac;
    const float* Wptr1 = W + (size_t)(n0 + ar + 64) * K + ac;

    float acc[8][8];
#pragma unroll
    for (int i = 0; i < 8; i++)
#pragma unroll
        for (int j = 0; j < 8; j++) acc[i][j] = 0.f;

    float4 a0 = *(const float4*)(Aptr0);
    float4 a1 = *(const float4*)(Aptr1);
    float4 w0 = *(const float4*)(Wptr0);
    float4 w1 = *(const float4*)(Wptr1);
    {
        As[0][ac+0][ar] = a0.x; As[0][ac+1][ar] = a0.y;
        As[0][ac+2][ar] = a0.z; As[0][ac+3][ar] = a0.w;
        As[0][ac+0][ar+64] = a1.x; As[0][ac+1][ar+64] = a1.y;
        As[0][ac+2][ar+64] = a1.z; As[0][ac+3][ar+64] = a1.w;
        Bs[0][ac+0][ar] = w0.x; Bs[0][ac+1][ar] = w0.y;
        Bs[0][ac+2][ar] = w0.z; Bs[0][ac+3][ar] = w0.w;
        Bs[0][ac+0][ar+64] = w1.x; Bs[0][ac+1][ar+64] = w1.y;
        Bs[0][ac+2][ar+64] = w1.z; Bs[0][ac+3][ar+64] = w1.w;
    }
    __syncthreads();

    int buf = 0;
    const int NT = K / BKg;
    for (int it = 1; it < NT; it++) {
        int k0 = it * BKg;
        a0 = *(const float4*)(Aptr0 + k0);
        a1 = *(const float4*)(Aptr1 + k0);
        w0 = *(const float4*)(Wptr0 + k0);
        w1 = *(const float4*)(Wptr1 + k0);

#pragma unroll
        for (int kk = 0; kk < BKg; kk++) {
            float4 av0 = *(const float4*)&As[buf][kk][ty*8];
            float4 av1 = *(const float4*)&As[buf][kk][ty*8+4];
            float4 bv0 = *(const float4*)&Bs[buf][kk][tx*8];
            float4 bv1 = *(const float4*)&Bs[buf][kk][tx*8+4];
            float af[8] = {av0.x,av0.y,av0.z,av0.w,av1.x,av1.y,av1.z,av1.w};
            float bf[8] = {bv0.x,bv0.y,bv0.z,bv0.w,bv1.x,bv1.y,bv1.z,bv1.w};
#pragma unroll
            for (int i = 0; i < 8; i++)
#pragma unroll
                for (int j = 0; j < 8; j++)
                    acc[i][j] += af[i] * bf[j];
        }

        int nb = buf ^ 1;
        As[nb][ac+0][ar] = a0.x; As[nb][ac+1][ar] = a0.y;
        As[nb][ac+2][ar] = a0.z; As[nb][ac+3][ar] = a0.w;
        As[nb][ac+0][ar+64] = a1.x; As[nb][ac+1][ar+64] = a1.y;
        As[nb][ac+2][ar+64] = a1.z; As[nb][ac+3][ar+64] = a1.w;
        Bs[nb][ac+0][ar] = w0.x; Bs[nb][ac+1][ar] = w0.y;
        Bs[nb][ac+2][ar] = w0.z; Bs[nb][ac+3][ar] = w0.w;
        Bs[nb][ac+0][ar+64] = w1.x; Bs[nb][ac+1][ar+64] = w1.y;
        Bs[nb][ac+2][ar+64] = w1.z; Bs[nb][ac+3][ar+64] = w1.w;
        __syncthreads();
        buf = nb;
    }

#pragma unroll
    for (int kk = 0; kk < BKg; kk++) {
        float4 av0 = *(const float4*)&As[buf][kk][ty*8];
        float4 av1 = *(const float4*)&As[buf][kk][ty*8+4];
        float4 bv0 = *(const float4*)&Bs[buf][kk][tx*8];
        float4 bv1 = *(const float4*)&Bs[buf][kk][tx*8+4];
        float af[8] = {av0.x,av0.y,av0.z,av0.w,av1.x,av1.y,av1.z,av1.w};
        float bf[8] = {bv0.x,bv0.y,bv0.z,bv0.w,bv1.x,bv1.y,bv1.z,bv1.w};
#pragma unroll
        for (int i = 0; i < 8; i++)
#pragma unroll
            for (int j = 0; j < 8; j++)
                acc[i][j] += af[i] * bf[j];
    }

    float bb[8];
#pragma unroll
    for (int j = 0; j < 8; j++) bb[j] = bias[n0 + tx*8 + j];

#pragma unroll
    for (int i = 0; i < 8; i++) {
        int row = m0 + ty*8 + i;
        float* orow = out + (size_t)row * N + n0 + tx*8;
        float4 r0, r1;
        r0.x = acc[i][0] + bb[0]; r0.y = acc[i][1] + bb[1];
        r0.z = acc[i][2] + bb[2]; r0.w = acc[i][3] + bb[3];
        r1.x = acc[i][4] + bb[4]; r1.y = acc[i][5] + bb[5];
        r1.z = acc[i][6] + bb[6]; r1.w = acc[i][7] + bb[7];
        *(float4*)(orow)     = r0;
        *(float4*)(orow + 4) = r1;
    }
}

__global__ __launch_bounds__(256)
void sgemm_qkv_kernel(const float* __restrict__ x,
                      const float* __restrict__ Wq, const float* __restrict__ bq,
                      const float* __restrict__ Wk, const float* __restrict__ bk,
                      const float* __restrict__ Wv, const float* __restrict__ bv)
{
    const float* W; const float* b; float* out;
    if (blockIdx.z == 0)      { W = Wq; b = bq; out = g_q; }
    else if (blockIdx.z == 1) { W = Wk; b = bk; out = g_k; }
    else                      { W = Wv; b = bv; out = g_v; }
    sgemm_body(x, W, b, out);
}

__global__ __launch_bounds__(256)
void sgemm_proj_kernel(const float* __restrict__ Wp, const float* __restrict__ bp,
                       float* __restrict__ out)
{
    sgemm_body(g_att, Wp, bp, out);
}

// ---------------------------------------------------------------------------
// RoPE in-place on g_q, g_k. Layout [B,T,H,D].
// ---------------------------------------------------------------------------
#define NPAIR (BB*TT*HH*32)

__global__ __launch_bounds__(256)
void rope_kernel()
{
    int idx = blockIdx.x * blockDim.x + threadIdx.x;
    if (idx >= 2 * NPAIR) return;
    float* arr = (idx < NPAIR) ? g_q : g_k;
    int i = (idx < NPAIR) ? idx : idx - NPAIR;
    int j = i & 31;
    int h = (i >> 5) & 15;
    int t = (i >> 9) & 2047;
    int b = i >> 20;
    const float L = 13.287712379549449f / 32.0f;  // log2(10000)/32
    float inv = exp2f(-(float)j * L);
    float ang = (float)t * inv;
    float c, s;
    sincosf(ang, &s, &c);
    float* p = arr + (((size_t)(b*TT + t))*HH + h) * DD;
    float x1 = p[j];
    float x2 = p[j + 32];
    p[j]      = x1 * c - x2 * s;
    p[j + 32] = x2 * c + x1 * s;
}

// ---------------------------------------------------------------------------
// Causal flash attention, fp32, GEMM-tiled.
// CTA: 256 threads, 64-query tile for one (b,h). Per K-tile of 64 keys:
//   S = Q K^T (64x64x64 smem GEMM, 4x4 microtile per thread)
//   online softmax per row (16-lane shuffle reductions)
//   P -> smem (reusing K buffer), O += P V (second smem GEMM)
// ---------------------------------------------------------------------------
#define ATT_STRIDE 68
#define ATT_SMEM_BYTES (3 * 64 * ATT_STRIDE * 4)   // 52224

__global__ __launch_bounds__(256)
void attn_kernel()
{
    extern __shared__ float sm[];
    float (*Qs)[ATT_STRIDE] = (float(*)[ATT_STRIDE])sm;
    float (*Ks)[ATT_STRIDE] = (float(*)[ATT_STRIDE])(sm + 64 * ATT_STRIDE);
    float (*Vs)[ATT_STRIDE] = (float(*)[ATT_STRIDE])(sm + 2 * 64 * ATT_STRIDE);
    float (*Ps)[ATT_STRIDE] = Ks;   // P reuses K buffer after S is computed

    int tid = threadIdx.x;
    int ty = tid >> 4;          // 0..15 -> 4 query rows
    int tx = tid & 15;          // 0..15 -> 4 key cols / 4 dim cols
    int qt = gridDim.x - 1 - blockIdx.x;   // largest work first
    int bh = blockIdx.y;
    int b = bh >> 4, h = bh & 15;
    int q0 = qt * 64;

    // Load Q tile [64 x 64] into smem
    const float* qbase = g_q + (((size_t)(b*TT + q0))*HH + h) * DD;
#pragma unroll
    for (int j = 0; j < 4; j++) {
        int idx = tid + 256*j;       // 0..1023
        int r = idx >> 4;
        int c4 = idx & 15;
        float4 v = ((const float4*)(qbase + (size_t)r * (HH*DD)))[c4];
        *(float4*)&Qs[r][c4*4] = v;
    }

    float o[4][4];
#pragma unroll
    for (int i = 0; i < 4; i++)
#pragma unroll
        for (int j = 0; j < 4; j++) o[i][j] = 0.f;
    float m[4], l[4];
#pragma unroll
    for (int i = 0; i < 4; i++) { m[i] = -1e30f; l[i] = 0.f; }

    for (int kt = 0; kt <= qt; kt++) {
        int k0 = kt * 64;
        const float* kbase = g_k + (((size_t)(b*TT + k0))*HH + h) * DD;
        const float* vbase = g_v + (((size_t)(b*TT + k0))*HH + h) * DD;

        __syncthreads();   // previous-iter consumers of Ks(Ps)/Vs done
#pragma unroll
        for (int j = 0; j < 4; j++) {
            int idx = tid + 256*j;
            int r = idx >> 4;
            int c4 = idx & 15;
            *(float4*)&Ks[r][c4*4] = ((const float4*)(kbase + (size_t)r * (HH*DD)))[c4];
            *(float4*)&Vs[r][c4*4] = ((const float4*)(vbase + (size_t)r * (HH*DD)))[c4];
        }
        __syncthreads();

        // S = Q K^T : each thread rows ty*4.., cols tx*4..
        float s[4][4];
#pragma unroll
        for (int i = 0; i < 4; i++)
#pragma unroll
            for (int j = 0; j < 4; j++) s[i][j] = 0.f;

#pragma unroll
        for (int kk4 = 0; kk4 < 16; kk4++) {
            float4 qv[4], kv[4];
#pragma unroll
            for (int i = 0; i < 4; i++) qv[i] = *(const float4*)&Qs[ty*4+i][kk4*4];
#pragma unroll
            for (int j = 0; j < 4; j++) kv[j] = *(const float4*)&Ks[tx*4+j][kk4*4];
#pragma unroll
            for (int i = 0; i < 4; i++)
#pragma unroll
                for (int j = 0; j < 4; j++)
                    s[i][j] += qv[i].x*kv[j].x + qv[i].y*kv[j].y
                             + qv[i].z*kv[j].z + qv[i].w*kv[j].w;
        }

        // scale + causal mask (only the diagonal tile needs masking)
        if (kt == qt) {
#pragma unroll
            for (int i = 0; i < 4; i++)
#pragma unroll
                for (int j = 0; j < 4; j++)
                    s[i][j] = (tx*4+j <= ty*4+i) ? s[i][j] * 0.125f : -1e30f;
        } else {
#pragma unroll
            for (int i = 0; i < 4; i++)
#pragma unroll
                for (int j = 0; j < 4; j++) s[i][j] *= 0.125f;
        }

        // online softmax per row; rows live in a 16-lane shuffle group
#pragma unroll
        for (int i = 0; i < 4; i++) {
            float rmax = fmaxf(fmaxf(s[i][0], s[i][1]), fmaxf(s[i][2], s[i][3]));
#pragma unroll
            for (int off = 1; off < 16; off <<= 1)
                rmax = fmaxf(rmax, __shfl_xor_sync(0xffffffffu, rmax, off));
            float nm = fmaxf(m[i], rmax);
            float corr = __expf(m[i] - nm);
            m[i] = nm;
            float rsum = 0.f;
#pragma unroll
            for (int j = 0; j < 4; j++) {
                s[i][j] = __expf(s[i][j] - nm);
                rsum += s[i][j];
            }
#pragma unroll
            for (int off = 1; off < 16; off <<= 1)
                rsum += __shfl_xor_sync(0xffffffffu, rsum, off);
            l[i] = l[i] * corr + rsum;
#pragma unroll
            for (int j = 0; j < 4; j++) o[i][j] *= corr;
        }

        __syncthreads();   // all threads done reading Ks before overwriting with P
#pragma unroll
        for (int i = 0; i < 4; i++) {
            float4 pv = make_float4(s[i][0], s[i][1], s[i][2], s[i][3]);
            *(float4*)&Ps[ty*4+i][tx*4] = pv;
        }
        __syncthreads();

        // O += P V : rows ty*4.., dim cols tx*4..
#pragma unroll
        for (int kk4 = 0; kk4 < 16; kk4++) {
            float4 pr[4], vv[4];
#pragma unroll
            for (int i = 0; i < 4; i++) pr[i] = *(const float4*)&Ps[ty*4+i][kk4*4];
#pragma unroll
            for (int jj = 0; jj < 4; jj++) vv[jj] = *(const float4*)&Vs[kk4*4+jj][tx*4];
#pragma unroll
            for (int i = 0; i < 4; i++) {
                o[i][0] += pr[i].x*vv[0].x + pr[i].y*vv[1].x + pr[i].z*vv[2].x + pr[i].w*vv[3].x;
                o[i][1] += pr[i].x*vv[0].y + pr[i].y*vv[1].y + pr[i].z*vv[2].y + pr[i].w*vv[3].y;
                o[i][2] += pr[i].x*vv[0].z + pr[i].y*vv[1].z + pr[i].z*vv[2].z + pr[i].w*vv[3].z;
                o[i][3] += pr[i].x*vv[0].w + pr[i].y*vv[1].w + pr[i].z*vv[2].w + pr[i].w*vv[3].w;
            }
        }
    }

    // epilogue: normalize and write [B,T,C] at col h*64 + tx*4
#pragma unroll
    for (int i = 0; i < 4; i++) {
        float inv = 1.f / l[i];
        float* yrow = g_att + ((size_t)(b*TT + q0 + ty*4 + i))*CC + h*DD + tx*4;
        float4 ov;
        ov.x = o[i][0] * inv; ov.y = o[i][1] * inv;
        ov.z = o[i][2] * inv; ov.w = o[i][3] * inv;
        *(float4*)yrow = ov;
    }
}

// ---------------------------------------------------------------------------
extern "C" void kernel_launch(void* const* d_in, const int* in_sizes, int n_in,
                              void* d_out, int out_size)
{
    const float* x  = (const float*)d_in[0];
    const float* Wq = (const float*)d_in[1];
    const float* bq = (const float*)d_in[2];
    const float* Wk = (const float*)d_in[3];
    const float* bk = (const float*)d_in[4];
    const float* Wv = (const float*)d_in[5];
    const float* bv = (const float*)d_in[6];
    const float* Wp = (const float*)d_in[7];
    const float* bp = (const float*)d_in[8];
    float* out = (float*)d_out;

    // one-time-safe, idempotent attribute set (not a stream op; capture-safe)
    cudaFuncSetAttribute(attn_kernel,
                         cudaFuncAttributeMaxDynamicSharedMemorySize,
                         ATT_SMEM_BYTES);

    dim3 gemm_grid(1024/128, 4096/128, 3);
    sgemm_qkv_kernel<<<gemm_grid, 256>>>(x, Wq, bq, Wk, bk, Wv, bv);

    int rope_threads = 2 * NPAIR;
    rope_kernel<<<(rope_threads + 255) / 256, 256>>>();

    dim3 attn_grid(TT/64, BB*HH);    // (32, 32)
    attn_kernel<<<attn_grid, 256, ATT_SMEM_BYTES>>>();

    dim3 proj_grid(1024/128, 4096/128);
    sgemm_proj_kernel<<<proj_grid, 256>>>(Wp, bp, out);
}

// round 5
// speedup vs baseline: 1.4276x; 1.2923x over previous
#include <cuda_runtime.h>
#include <math.h>
#include <stdint.h>

// Problem constants
#define BB 2
#define TT 2048
#define HH 16
#define DD 64
#define CC 1024
#define MM (BB*TT)   // 4096

// Scratch (allocation-free rule: __device__ globals)
__device__ float g_q[MM*CC];
__device__ float g_k[MM*CC];
__device__ float g_v[MM*CC];
__device__ float g_att[MM*CC];

// ---------------------------------------------------------------------------
// tf32 helpers
// ---------------------------------------------------------------------------
__device__ __forceinline__ float to_tf32(float x) {
    float r;
    asm("cvt.rna.tf32.f32 %0, %1;" : "=f"(r) : "f"(x));
    return r;
}

__device__ __forceinline__ void mma_tf32(float c[4], const uint32_t a[4],
                                         const uint32_t b[2])
{
    asm volatile(
        "mma.sync.aligned.m16n8k8.row.col.f32.tf32.tf32.f32 "
        "{%0,%1,%2,%3}, {%4,%5,%6,%7}, {%8,%9}, {%0,%1,%2,%3};"
        : "+f"(c[0]), "+f"(c[1]), "+f"(c[2]), "+f"(c[3])
        : "r"(a[0]), "r"(a[1]), "r"(a[2]), "r"(a[3]),
          "r"(b[0]), "r"(b[1]));
}

// ===========================================================================
// tf32 mma.sync GEMM: out[m,n] = sum_k A[m,k]*W[n,k] + bias[n]
// M=4096, N=1024, K=1024. BM=BN=128, BK=16, 256 thr (8 warps, 4x2).
// Warp tile 32x64 = 2x8 m16n8k8 fragments. Smem k-major, double-buffered.
// ===========================================================================
#define GK 1024
#define GN 1024
#define BKt 16
#define SPAD 132

__device__ __forceinline__ void mm128_body(
    const float* __restrict__ A, const float* __restrict__ W,
    const float* __restrict__ bias, float* __restrict__ out)
{
    __shared__ float As[2][BKt][SPAD];
    __shared__ float Bs[2][BKt][SPAD];

    int tid = threadIdx.x;
    int wid = tid >> 5;
    int lane = tid & 31;
    int grp = lane >> 2;       // 0..7
    int tig = lane & 3;        // 0..3
    int wm = wid >> 1;         // 0..3  -> 32-row slab
    int wn = wid & 1;          // 0..1  -> 64-col slab

    int m0 = blockIdx.y * 128;
    int n0 = blockIdx.x * 128;

    // loader mapping: idx in [0,512): r = idx>>2 (0..127), c4 = idx&3
    int r0 = tid >> 2;          // rows r0 and r0+64
    int c40 = (tid & 3) * 4;    // k-offset 0,4,8,12

    const float* Ag0 = A + (size_t)(m0 + r0) * GK + c40;
    const float* Ag1 = A + (size_t)(m0 + r0 + 64) * GK + c40;
    const float* Wg0 = W + (size_t)(n0 + r0) * GK + c40;
    const float* Wg1 = W + (size_t)(n0 + r0 + 64) * GK + c40;

    float c[2][8][4];
#pragma unroll
    for (int mt = 0; mt < 2; mt++)
#pragma unroll
        for (int nt = 0; nt < 8; nt++)
#pragma unroll
            for (int i = 0; i < 4; i++) c[mt][nt][i] = 0.f;

    // prefetch tile 0
    float4 a0 = *(const float4*)(Ag0);
    float4 a1 = *(const float4*)(Ag1);
    float4 w0 = *(const float4*)(Wg0);
    float4 w1 = *(const float4*)(Wg1);

#define STORE_TILE(buf)                                                     \
    do {                                                                    \
        As[buf][c40+0][r0]    = to_tf32(a0.x);                              \
        As[buf][c40+1][r0]    = to_tf32(a0.y);                              \
        As[buf][c40+2][r0]    = to_tf32(a0.z);                              \
        As[buf][c40+3][r0]    = to_tf32(a0.w);                              \
        As[buf][c40+0][r0+64] = to_tf32(a1.x);                              \
        As[buf][c40+1][r0+64] = to_tf32(a1.y);                              \
        As[buf][c40+2][r0+64] = to_tf32(a1.z);                              \
        As[buf][c40+3][r0+64] = to_tf32(a1.w);                              \
        Bs[buf][c40+0][r0]    = to_tf32(w0.x);                              \
        Bs[buf][c40+1][r0]    = to_tf32(w0.y);                              \
        Bs[buf][c40+2][r0]    = to_tf32(w0.z);                              \
        Bs[buf][c40+3][r0]    = to_tf32(w0.w);                              \
        Bs[buf][c40+0][r0+64] = to_tf32(w1.x);                              \
        Bs[buf][c40+1][r0+64] = to_tf32(w1.y);                              \
        Bs[buf][c40+2][r0+64] = to_tf32(w1.z);                              \
        Bs[buf][c40+3][r0+64] = to_tf32(w1.w);                              \
    } while (0)

#define COMPUTE_TILE(buf)                                                   \
    do {                                                                    \
        _Pragma("unroll")                                                   \
        for (int ks = 0; ks < 2; ks++) {                                    \
            int kk = ks * 8;                                                \
            uint32_t afr[2][4];                                             \
            _Pragma("unroll")                                               \
            for (int mt = 0; mt < 2; mt++) {                                \
                int rm = wm*32 + mt*16;                                     \
                afr[mt][0] = __float_as_uint(As[buf][kk+tig][rm+grp]);      \
                afr[mt][1] = __float_as_uint(As[buf][kk+tig][rm+grp+8]);    \
                afr[mt][2] = __float_as_uint(As[buf][kk+tig+4][rm+grp]);    \
                afr[mt][3] = __float_as_uint(As[buf][kk+tig+4][rm+grp+8]);  \
            }                                                               \
            uint32_t bfr[8][2];                                             \
            _Pragma("unroll")                                               \
            for (int nt = 0; nt < 8; nt++) {                                \
                int cn = wn*64 + nt*8;                                      \
                bfr[nt][0] = __float_as_uint(Bs[buf][kk+tig][cn+grp]);      \
                bfr[nt][1] = __float_as_uint(Bs[buf][kk+tig+4][cn+grp]);    \
            }                                                               \
            _Pragma("unroll")                                               \
            for (int mt = 0; mt < 2; mt++)                                  \
                _Pragma("unroll")                                           \
                for (int nt = 0; nt < 8; nt++)                              \
                    mma_tf32(c[mt][nt], afr[mt], bfr[nt]);                  \
        }                                                                   \
    } while (0)

    STORE_TILE(0);
    __syncthreads();

    const int NT = GK / BKt;   // 64
    for (int it = 1; it < NT; it++) {
        int k0 = it * BKt;
        a0 = *(const float4*)(Ag0 + k0);
        a1 = *(const float4*)(Ag1 + k0);
        w0 = *(const float4*)(Wg0 + k0);
        w1 = *(const float4*)(Wg1 + k0);

        int buf = (it - 1) & 1;
        COMPUTE_TILE(buf);

        int nb = it & 1;
        __syncthreads();       // everyone done reading buf "nb" from 2 iters ago
        STORE_TILE(nb);
        __syncthreads();
    }
    COMPUTE_TILE((NT - 1) & 1);

#undef STORE_TILE
#undef COMPUTE_TILE

    // epilogue: c0,c1 -> (row, col),(row,col+1); c2,c3 -> (row+8, ...)
#pragma unroll
    for (int mt = 0; mt < 2; mt++) {
        int row = m0 + wm*32 + mt*16 + grp;
#pragma unroll
        for (int nt = 0; nt < 8; nt++) {
            int col = n0 + wn*64 + nt*8 + tig*2;
            float2 bv = *(const float2*)(bias + col);
            float2 o0, o1;
            o0.x = c[mt][nt][0] + bv.x;
            o0.y = c[mt][nt][1] + bv.y;
            o1.x = c[mt][nt][2] + bv.x;
            o1.y = c[mt][nt][3] + bv.y;
            *(float2*)(out + (size_t)row * GN + col) = o0;
            *(float2*)(out + (size_t)(row + 8) * GN + col) = o1;
        }
    }
}

__global__ __launch_bounds__(256)
void mm_qkv_kernel(const float* __restrict__ x,
                   const float* __restrict__ Wq, const float* __restrict__ bq,
                   const float* __restrict__ Wk, const float* __restrict__ bk,
                   const float* __restrict__ Wv, const float* __restrict__ bv)
{
    const float* W; const float* b; float* out;
    if (blockIdx.z == 0)      { W = Wq; b = bq; out = g_q; }
    else if (blockIdx.z == 1) { W = Wk; b = bk; out = g_k; }
    else                      { W = Wv; b = bv; out = g_v; }
    mm128_body(x, W, b, out);
}

__global__ __launch_bounds__(256)
void mm_proj_kernel(const float* __restrict__ Wp, const float* __restrict__ bp,
                    float* __restrict__ out)
{
    mm128_body(g_att, Wp, bp, out);
}

// ---------------------------------------------------------------------------
// RoPE in-place on g_q, g_k. Layout [B,T,H,D].
// ---------------------------------------------------------------------------
#define NPAIR (BB*TT*HH*32)

__global__ __launch_bounds__(256)
void rope_kernel()
{
    int idx = blockIdx.x * blockDim.x + threadIdx.x;
    if (idx >= 2 * NPAIR) return;
    float* arr = (idx < NPAIR) ? g_q : g_k;
    int i = (idx < NPAIR) ? idx : idx - NPAIR;
    int j = i & 31;
    int h = (i >> 5) & 15;
    int t = (i >> 9) & 2047;
    int b = i >> 20;
    const float L = 13.287712379549449f / 32.0f;  // log2(10000)/32
    float inv = exp2f(-(float)j * L);
    float ang = (float)t * inv;
    float c, s;
    sincosf(ang, &s, &c);
    float* p = arr + (((size_t)(b*TT + t))*HH + h) * DD;
    float x1 = p[j];
    float x2 = p[j + 32];
    p[j]      = x1 * c - x2 * s;
    p[j + 32] = x2 * c + x1 * s;
}

// ---------------------------------------------------------------------------
// Causal flash attention, fp32, GEMM-tiled. (Unchanged from R3.)
// ---------------------------------------------------------------------------
#define ATT_STRIDE 68
#define ATT_SMEM_BYTES (3 * 64 * ATT_STRIDE * 4)   // 52224

__global__ __launch_bounds__(256)
void attn_kernel()
{
    extern __shared__ float sm[];
    float (*Qs)[ATT_STRIDE] = (float(*)[ATT_STRIDE])sm;
    float (*Ks)[ATT_STRIDE] = (float(*)[ATT_STRIDE])(sm + 64 * ATT_STRIDE);
    float (*Vs)[ATT_STRIDE] = (float(*)[ATT_STRIDE])(sm + 2 * 64 * ATT_STRIDE);
    float (*Ps)[ATT_STRIDE] = Ks;

    int tid = threadIdx.x;
    int ty = tid >> 4;
    int tx = tid & 15;
    int qt = gridDim.x - 1 - blockIdx.x;
    int bh = blockIdx.y;
    int b = bh >> 4, h = bh & 15;
    int q0 = qt * 64;

    const float* qbase = g_q + (((size_t)(b*TT + q0))*HH + h) * DD;
#pragma unroll
    for (int j = 0; j < 4; j++) {
        int idx = tid + 256*j;
        int r = idx >> 4;
        int c4 = idx & 15;
        float4 v = ((const float4*)(qbase + (size_t)r * (HH*DD)))[c4];
        *(float4*)&Qs[r][c4*4] = v;
    }

    float o[4][4];
#pragma unroll
    for (int i = 0; i < 4; i++)
#pragma unroll
        for (int j = 0; j < 4; j++) o[i][j] = 0.f;
    float m[4], l[4];
#pragma unroll
    for (int i = 0; i < 4; i++) { m[i] = -1e30f; l[i] = 0.f; }

    for (int kt = 0; kt <= qt; kt++) {
        int k0 = kt * 64;
        const float* kbase = g_k + (((size_t)(b*TT + k0))*HH + h) * DD;
        const float* vbase = g_v + (((size_t)(b*TT + k0))*HH + h) * DD;

        __syncthreads();
#pragma unroll
        for (int j = 0; j < 4; j++) {
            int idx = tid + 256*j;
            int r = idx >> 4;
            int c4 = idx & 15;
            *(float4*)&Ks[r][c4*4] = ((const float4*)(kbase + (size_t)r * (HH*DD)))[c4];
            *(float4*)&Vs[r][c4*4] = ((const float4*)(vbase + (size_t)r * (HH*DD)))[c4];
        }
        __syncthreads();

        float s[4][4];
#pragma unroll
        for (int i = 0; i < 4; i++)
#pragma unroll
            for (int j = 0; j < 4; j++) s[i][j] = 0.f;

#pragma unroll
        for (int kk4 = 0; kk4 < 16; kk4++) {
            float4 qv[4], kv[4];
#pragma unroll
            for (int i = 0; i < 4; i++) qv[i] = *(const float4*)&Qs[ty*4+i][kk4*4];
#pragma unroll
            for (int j = 0; j < 4; j++) kv[j] = *(const float4*)&Ks[tx*4+j][kk4*4];
#pragma unroll
            for (int i = 0; i < 4; i++)
#pragma unroll
                for (int j = 0; j < 4; j++)
                    s[i][j] += qv[i].x*kv[j].x + qv[i].y*kv[j].y
                             + qv[i].z*kv[j].z + qv[i].w*kv[j].w;
        }

        if (kt == qt) {
#pragma unroll
            for (int i = 0; i < 4; i++)
#pragma unroll
                for (int j = 0; j < 4; j++)
                    s[i][j] = (tx*4+j <= ty*4+i) ? s[i][j] * 0.125f : -1e30f;
        } else {
#pragma unroll
            for (int i = 0; i < 4; i++)
#pragma unroll
                for (int j = 0; j < 4; j++) s[i][j] *= 0.125f;
        }

#pragma unroll
        for (int i = 0; i < 4; i++) {
            float rmax = fmaxf(fmaxf(s[i][0], s[i][1]), fmaxf(s[i][2], s[i][3]));
#pragma unroll
            for (int off = 1; off < 16; off <<= 1)
                rmax = fmaxf(rmax, __shfl_xor_sync(0xffffffffu, rmax, off));
            float nm = fmaxf(m[i], rmax);
            float corr = __expf(m[i] - nm);
            m[i] = nm;
            float rsum = 0.f;
#pragma unroll
            for (int j = 0; j < 4; j++) {
                s[i][j] = __expf(s[i][j] - nm);
                rsum += s[i][j];
            }
#pragma unroll
            for (int off = 1; off < 16; off <<= 1)
                rsum += __shfl_xor_sync(0xffffffffu, rsum, off);
            l[i] = l[i] * corr + rsum;
#pragma unroll
            for (int j = 0; j < 4; j++) o[i][j] *= corr;
        }

        __syncthreads();
#pragma unroll
        for (int i = 0; i < 4; i++) {
            float4 pv = make_float4(s[i][0], s[i][1], s[i][2], s[i][3]);
            *(float4*)&Ps[ty*4+i][tx*4] = pv;
        }
        __syncthreads();

#pragma unroll
        for (int kk4 = 0; kk4 < 16; kk4++) {
            float4 pr[4], vv[4];
#pragma unroll
            for (int i = 0; i < 4; i++) pr[i] = *(const float4*)&Ps[ty*4+i][kk4*4];
#pragma unroll
            for (int jj = 0; jj < 4; jj++) vv[jj] = *(const float4*)&Vs[kk4*4+jj][tx*4];
#pragma unroll
            for (int i = 0; i < 4; i++) {
                o[i][0] += pr[i].x*vv[0].x + pr[i].y*vv[1].x + pr[i].z*vv[2].x + pr[i].w*vv[3].x;
                o[i][1] += pr[i].x*vv[0].y + pr[i].y*vv[1].y + pr[i].z*vv[2].y + pr[i].w*vv[3].y;
                o[i][2] += pr[i].x*vv[0].z + pr[i].y*vv[1].z + pr[i].z*vv[2].z + pr[i].w*vv[3].z;
                o[i][3] += pr[i].x*vv[0].w + pr[i].y*vv[1].w + pr[i].z*vv[2].w + pr[i].w*vv[3].w;
            }
        }
    }

#pragma unroll
    for (int i = 0; i < 4; i++) {
        float inv = 1.f / l[i];
        float* yrow = g_att + ((size_t)(b*TT + q0 + ty*4 + i))*CC + h*DD + tx*4;
        float4 ov;
        ov.x = o[i][0] * inv; ov.y = o[i][1] * inv;
        ov.z = o[i][2] * inv; ov.w = o[i][3] * inv;
        *(float4*)yrow = ov;
    }
}

// ---------------------------------------------------------------------------
extern "C" void kernel_launch(void* const* d_in, const int* in_sizes, int n_in,
                              void* d_out, int out_size)
{
    const float* x  = (const float*)d_in[0];
    const float* Wq = (const float*)d_in[1];
    const float* bq = (const float*)d_in[2];
    const float* Wk = (const float*)d_in[3];
    const float* bk = (const float*)d_in[4];
    const float* Wv = (const float*)d_in[5];
    const float* bv = (const float*)d_in[6];
    const float* Wp = (const float*)d_in[7];
    const float* bp = (const float*)d_in[8];
    float* out = (float*)d_out;

    cudaFuncSetAttribute(attn_kernel,
                         cudaFuncAttributeMaxDynamicSharedMemorySize,
                         ATT_SMEM_BYTES);

    // 1. QKV projections on tf32 mma.sync
    dim3 qkv_grid(GN/128, MM/128, 3);   // (8, 32, 3)
    mm_qkv_kernel<<<qkv_grid, 256>>>(x, Wq, bq, Wk, bk, Wv, bv);

    // 2. RoPE
    int rope_threads = 2 * NPAIR;
    rope_kernel<<<(rope_threads + 255) / 256, 256>>>();

    // 3. Attention
    dim3 attn_grid(TT/64, BB*HH);       // (32, 32)
    attn_kernel<<<attn_grid, 256, ATT_SMEM_BYTES>>>();

    // 4. Output projection on tf32 mma.sync
    dim3 proj_grid(GN/128, MM/128);
    mm_proj_kernel<<<proj_grid, 256>>>(Wp, bp, out);
}

// round 7
// speedup vs baseline: 2.1868x; 1.5318x over previous
#include <cuda_runtime.h>
#include <math.h>
#include <stdint.h>

// Problem constants
#define BB 2
#define TT 2048
#define HH 16
#define DD 64
#define CC 1024
#define MM (BB*TT)   // 4096

// Scratch (allocation-free rule: __device__ globals)
__device__ float g_q[MM*CC];
__device__ float g_k[MM*CC];
__device__ float g_v[MM*CC];
__device__ float g_att[MM*CC];

// ---------------------------------------------------------------------------
// tf32 helpers
// ---------------------------------------------------------------------------
__device__ __forceinline__ float to_tf32(float x) {
    float r;
    asm("cvt.rna.tf32.f32 %0, %1;" : "=f"(r) : "f"(x));
    return r;
}

__device__ __forceinline__ void mma_tf32(float c[4], const uint32_t a[4],
                                         const uint32_t b[2])
{
    asm volatile(
        "mma.sync.aligned.m16n8k8.row.col.f32.tf32.tf32.f32 "
        "{%0,%1,%2,%3}, {%4,%5,%6,%7}, {%8,%9}, {%0,%1,%2,%3};"
        : "+f"(c[0]), "+f"(c[1]), "+f"(c[2]), "+f"(c[3])
        : "r"(a[0]), "r"(a[1]), "r"(a[2]), "r"(a[3]),
          "r"(b[0]), "r"(b[1]));
}

// ===========================================================================
// tf32 mma.sync GEMM (unchanged from R5 — confirmed 105us each)
// out[m,n] = sum_k A[m,k]*W[n,k] + bias[n]
// ===========================================================================
#define GK 1024
#define GN 1024
#define BKt 16
#define SPAD 132

__device__ __forceinline__ void mm128_body(
    const float* __restrict__ A, const float* __restrict__ W,
    const float* __restrict__ bias, float* __restrict__ out)
{
    __shared__ float As[2][BKt][SPAD];
    __shared__ float Bs[2][BKt][SPAD];

    int tid = threadIdx.x;
    int wid = tid >> 5;
    int lane = tid & 31;
    int grp = lane >> 2;
    int tig = lane & 3;
    int wm = wid >> 1;
    int wn = wid & 1;

    int m0 = blockIdx.y * 128;
    int n0 = blockIdx.x * 128;

    int r0 = tid >> 2;
    int c40 = (tid & 3) * 4;

    const float* Ag0 = A + (size_t)(m0 + r0) * GK + c40;
    const float* Ag1 = A + (size_t)(m0 + r0 + 64) * GK + c40;
    const float* Wg0 = W + (size_t)(n0 + r0) * GK + c40;
    const float* Wg1 = W + (size_t)(n0 + r0 + 64) * GK + c40;

    float c[2][8][4];
#pragma unroll
    for (int mt = 0; mt < 2; mt++)
#pragma unroll
        for (int nt = 0; nt < 8; nt++)
#pragma unroll
            for (int i = 0; i < 4; i++) c[mt][nt][i] = 0.f;

    float4 a0 = *(const float4*)(Ag0);
    float4 a1 = *(const float4*)(Ag1);
    float4 w0 = *(const float4*)(Wg0);
    float4 w1 = *(const float4*)(Wg1);

#define STORE_TILE(buf)                                                     \
    do {                                                                    \
        As[buf][c40+0][r0]    = to_tf32(a0.x);                              \
        As[buf][c40+1][r0]    = to_tf32(a0.y);                              \
        As[buf][c40+2][r0]    = to_tf32(a0.z);                              \
        As[buf][c40+3][r0]    = to_tf32(a0.w);                              \
        As[buf][c40+0][r0+64] = to_tf32(a1.x);                              \
        As[buf][c40+1][r0+64] = to_tf32(a1.y);                              \
        As[buf][c40+2][r0+64] = to_tf32(a1.z);                              \
        As[buf][c40+3][r0+64] = to_tf32(a1.w);                              \
        Bs[buf][c40+0][r0]    = to_tf32(w0.x);                              \
        Bs[buf][c40+1][r0]    = to_tf32(w0.y);                              \
        Bs[buf][c40+2][r0]    = to_tf32(w0.z);                              \
        Bs[buf][c40+3][r0]    = to_tf32(w0.w);                              \
        Bs[buf][c40+0][r0+64] = to_tf32(w1.x);                              \
        Bs[buf][c40+1][r0+64] = to_tf32(w1.y);                              \
        Bs[buf][c40+2][r0+64] = to_tf32(w1.z);                              \
        Bs[buf][c40+3][r0+64] = to_tf32(w1.w);                              \
    } while (0)

#define COMPUTE_TILE(buf)                                                   \
    do {                                                                    \
        _Pragma("unroll")                                                   \
        for (int ks = 0; ks < 2; ks++) {                                    \
            int kk = ks * 8;                                                \
            uint32_t afr[2][4];                                             \
            _Pragma("unroll")                                               \
            for (int mt = 0; mt < 2; mt++) {                                \
                int rm = wm*32 + mt*16;                                     \
                afr[mt][0] = __float_as_uint(As[buf][kk+tig][rm+grp]);      \
                afr[mt][1] = __float_as_uint(As[buf][kk+tig][rm+grp+8]);    \
                afr[mt][2] = __float_as_uint(As[buf][kk+tig+4][rm+grp]);    \
                afr[mt][3] = __float_as_uint(As[buf][kk+tig+4][rm+grp+8]);  \
            }                                                               \
            uint32_t bfr[8][2];                                             \
            _Pragma("unroll")                                               \
            for (int nt = 0; nt < 8; nt++) {                                \
                int cn = wn*64 + nt*8;                                      \
                bfr[nt][0] = __float_as_uint(Bs[buf][kk+tig][cn+grp]);      \
                bfr[nt][1] = __float_as_uint(Bs[buf][kk+tig+4][cn+grp]);    \
            }                                                               \
            _Pragma("unroll")                                               \
            for (int mt = 0; mt < 2; mt++)                                  \
                _Pragma("unroll")                                           \
                for (int nt = 0; nt < 8; nt++)                              \
                    mma_tf32(c[mt][nt], afr[mt], bfr[nt]);                  \
        }                                                                   \
    } while (0)

    STORE_TILE(0);
    __syncthreads();

    const int NT = GK / BKt;
    for (int it = 1; it < NT; it++) {
        int k0 = it * BKt;
        a0 = *(const float4*)(Ag0 + k0);
        a1 = *(const float4*)(Ag1 + k0);
        w0 = *(const float4*)(Wg0 + k0);
        w1 = *(const float4*)(Wg1 + k0);

        int buf = (it - 1) & 1;
        COMPUTE_TILE(buf);

        int nb = it & 1;
        __syncthreads();
        STORE_TILE(nb);
        __syncthreads();
    }
    COMPUTE_TILE((NT - 1) & 1);

#undef STORE_TILE
#undef COMPUTE_TILE

#pragma unroll
    for (int mt = 0; mt < 2; mt++) {
        int row = m0 + wm*32 + mt*16 + grp;
#pragma unroll
        for (int nt = 0; nt < 8; nt++) {
            int col = n0 + wn*64 + nt*8 + tig*2;
            float2 bv = *(const float2*)(bias + col);
            float2 o0, o1;
            o0.x = c[mt][nt][0] + bv.x;
            o0.y = c[mt][nt][1] + bv.y;
            o1.x = c[mt][nt][2] + bv.x;
            o1.y = c[mt][nt][3] + bv.y;
            *(float2*)(out + (size_t)row * GN + col) = o0;
            *(float2*)(out + (size_t)(row + 8) * GN + col) = o1;
        }
    }
}

__global__ __launch_bounds__(256)
void mm_qkv_kernel(const float* __restrict__ x,
                   const float* __restrict__ Wq, const float* __restrict__ bq,
                   const float* __restrict__ Wk, const float* __restrict__ bk,
                   const float* __restrict__ Wv, const float* __restrict__ bv)
{
    const float* W; const float* b; float* out;
    if (blockIdx.z == 0)      { W = Wq; b = bq; out = g_q; }
    else if (blockIdx.z == 1) { W = Wk; b = bk; out = g_k; }
    else                      { W = Wv; b = bv; out = g_v; }
    mm128_body(x, W, b, out);
}

__global__ __launch_bounds__(256)
void mm_proj_kernel(const float* __restrict__ Wp, const float* __restrict__ bp,
                    float* __restrict__ out)
{
    mm128_body(g_att, Wp, bp, out);
}

// ---------------------------------------------------------------------------
// RoPE in-place on g_q, g_k. Layout [B,T,H,D].
// ---------------------------------------------------------------------------
#define NPAIR (BB*TT*HH*32)

__global__ __launch_bounds__(256)
void rope_kernel()
{
    int idx = blockIdx.x * blockDim.x + threadIdx.x;
    if (idx >= 2 * NPAIR) return;
    float* arr = (idx < NPAIR) ? g_q : g_k;
    int i = (idx < NPAIR) ? idx : idx - NPAIR;
    int j = i & 31;
    int h = (i >> 5) & 15;
    int t = (i >> 9) & 2047;
    int b = i >> 20;
    const float L = 13.287712379549449f / 32.0f;  // log2(10000)/32
    float inv = exp2f(-(float)j * L);
    float ang = (float)t * inv;
    float c, s;
    sincosf(ang, &s, &c);
    float* p = arr + (((size_t)(b*TT + t))*HH + h) * DD;
    float x1 = p[j];
    float x2 = p[j + 32];
    p[j]      = x1 * c - x2 * s;
    p[j + 32] = x2 * c + x1 * s;
}

// ===========================================================================
// Tensor-core causal flash attention, tf32 mma with hi/lo compensation.
// CTA: 256 thr / 8 warps, 128 queries for one (b,h). Key tiles of 64.
// Each warp: 16 query rows x 64 key cols.
//   S = Qhi*Khi + Qhi*Klo + Qlo*Khi   (3x m16n8k8)
//   online softmax on C fragments (quad shuffles)
//   P -> smem (warp-private rows), split at load
//   O += Phi*Vhi + Phi*Vlo + Plo*Vhi  (3x m16n8k8)
// Smem: Khl[64][68] float2 (hi,lo), Vhl[64][68] float2, Ps[128][72] float.
// ===========================================================================
#define KHL_STRIDE 68
#define PS_STRIDE 72
#define ATT_SMEM_BYTES (64*KHL_STRIDE*8*2 + 128*PS_STRIDE*4)  // 106496

__global__ __launch_bounds__(256)
void attn_kernel()
{
    extern __shared__ float smf[];
    float2* Khl = (float2*)smf;                    // [64][68]
    float2* Vhl = Khl + 64*KHL_STRIDE;             // [64][68]
    float*  Ps  = (float*)(Vhl + 64*KHL_STRIDE);   // [128][72]

    const int tid = threadIdx.x;
    const int lane = tid & 31, wid = tid >> 5;
    const int grp = lane >> 2, tig = lane & 3;
    const int qtile = gridDim.x - 1 - blockIdx.x;   // big work first
    const int bh = blockIdx.y;
    const int b = bh >> 4, h = bh & 15;
    const int q0 = qtile * 128;
    const int wr0 = wid * 16;                       // warp row offset (local)

    // ---- stage Q (128 rows x 64 cols = 2048 float4) into Ps ----
    const float* qbase = g_q + (((size_t)(b*TT + q0))*HH + h) * DD;
#pragma unroll
    for (int j = 0; j < 8; j++) {
        int idx = tid + 256*j;          // 0..2047
        int r = idx >> 4, c4 = idx & 15;
        float4 v = ((const float4*)(qbase + (size_t)r * (HH*DD)))[c4];
        *(float4*)&Ps[r*PS_STRIDE + c4*4] = v;
    }
    __syncthreads();

    uint32_t qhi[8][4], qlo[8][4];
#pragma unroll
    for (int ks = 0; ks < 8; ks++) {
        float qv[4];
        qv[0] = Ps[(wr0+grp)  *PS_STRIDE + ks*8 + tig];
        qv[1] = Ps[(wr0+grp+8)*PS_STRIDE + ks*8 + tig];
        qv[2] = Ps[(wr0+grp)  *PS_STRIDE + ks*8 + tig + 4];
        qv[3] = Ps[(wr0+grp+8)*PS_STRIDE + ks*8 + tig + 4];
#pragma unroll
        for (int e = 0; e < 4; e++) {
            float hi = to_tf32(qv[e]);
            qhi[ks][e] = __float_as_uint(hi);
            qlo[ks][e] = __float_as_uint(to_tf32(qv[e] - hi));
        }
    }
    __syncwarp();

    float o[8][4];
#pragma unroll
    for (int nt = 0; nt < 8; nt++)
#pragma unroll
        for (int e = 0; e < 4; e++) o[nt][e] = 0.f;
    float mr0 = -1e30f, mr1 = -1e30f, lr0 = 0.f, lr1 = 0.f;

    const int row0 = q0 + wr0 + grp;
    const int row1 = row0 + 8;
    const int ntiles = 2*qtile + 2;

    for (int kt = 0; kt < ntiles; kt++) {
        int k0 = kt * 64;
        __syncthreads();   // previous tile's consumers of Khl/Vhl done

        // ---- cooperative K/V tile load (64 rows), hi/lo split at store ----
        const float* kb = g_k + (((size_t)(b*TT + k0))*HH + h) * DD;
        const float* vb = g_v + (((size_t)(b*TT + k0))*HH + h) * DD;
#pragma unroll
        for (int j = 0; j < 4; j++) {
            int idx = tid + 256*j;
            int r = idx >> 4, c4 = idx & 15;
            float4 kv = ((const float4*)(kb + (size_t)r * (HH*DD)))[c4];
            float hx = to_tf32(kv.x), hy = to_tf32(kv.y);
            float hz = to_tf32(kv.z), hw = to_tf32(kv.w);
            float4 p0 = make_float4(hx, to_tf32(kv.x - hx), hy, to_tf32(kv.y - hy));
            float4 p1 = make_float4(hz, to_tf32(kv.z - hz), hw, to_tf32(kv.w - hw));
            *(float4*)&Khl[r*KHL_STRIDE + c4*4]     = p0;
            *(float4*)&Khl[r*KHL_STRIDE + c4*4 + 2] = p1;

            float4 vv = ((const float4*)(vb + (size_t)r * (HH*DD)))[c4];
            hx = to_tf32(vv.x); hy = to_tf32(vv.y);
            hz = to_tf32(vv.z); hw = to_tf32(vv.w);
            p0 = make_float4(hx, to_tf32(vv.x - hx), hy, to_tf32(vv.y - hy));
            p1 = make_float4(hz, to_tf32(vv.z - hz), hw, to_tf32(vv.w - hw));
            *(float4*)&Vhl[r*KHL_STRIDE + c4*4]     = p0;
            *(float4*)&Vhl[r*KHL_STRIDE + c4*4 + 2] = p1;
        }
        __syncthreads();

        // warp entirely above this key tile (all cols in the future): skip
        if (k0 > q0 + wr0 + 15) continue;

        // ---- S = Q K^T (compensated) ----
        float c[8][4];
#pragma unroll
        for (int nt = 0; nt < 8; nt++)
#pragma unroll
            for (int e = 0; e < 4; e++) c[nt][e] = 0.f;

#pragma unroll
        for (int ks = 0; ks < 8; ks++) {
#pragma unroll
            for (int nt = 0; nt < 8; nt++) {
                float2 k0v = Khl[(nt*8+grp)*KHL_STRIDE + ks*8 + tig];
                float2 k1v = Khl[(nt*8+grp)*KHL_STRIDE + ks*8 + tig + 4];
                uint32_t bhi[2] = {__float_as_uint(k0v.x), __float_as_uint(k1v.x)};
                uint32_t blo[2] = {__float_as_uint(k0v.y), __float_as_uint(k1v.y)};
                mma_tf32(c[nt], qhi[ks], bhi);
                mma_tf32(c[nt], qhi[ks], blo);
                mma_tf32(c[nt], qlo[ks], bhi);
            }
        }

        // ---- scale + causal mask ----
#pragma unroll
        for (int nt = 0; nt < 8; nt++) {
            int col = k0 + nt*8 + tig*2;
            c[nt][0] = (col     <= row0) ? c[nt][0] * 0.125f : -1e30f;
            c[nt][1] = (col + 1 <= row0) ? c[nt][1] * 0.125f : -1e30f;
            c[nt][2] = (col     <= row1) ? c[nt][2] * 0.125f : -1e30f;
            c[nt][3] = (col + 1 <= row1) ? c[nt][3] * 0.125f : -1e30f;
        }

        // ---- online softmax (rows live in 4-lane quads) ----
        float mx0 = -1e30f, mx1 = -1e30f;
#pragma unroll
        for (int nt = 0; nt < 8; nt++) {
            mx0 = fmaxf(mx0, fmaxf(c[nt][0], c[nt][1]));
            mx1 = fmaxf(mx1, fmaxf(c[nt][2], c[nt][3]));
        }
        mx0 = fmaxf(mx0, __shfl_xor_sync(0xffffffffu, mx0, 1));
        mx0 = fmaxf(mx0, __shfl_xor_sync(0xffffffffu, mx0, 2));
        mx1 = fmaxf(mx1, __shfl_xor_sync(0xffffffffu, mx1, 1));
        mx1 = fmaxf(mx1, __shfl_xor_sync(0xffffffffu, mx1, 2));

        float nm0 = fmaxf(mr0, mx0), nm1 = fmaxf(mr1, mx1);
        float corr0 = __expf(mr0 - nm0), corr1 = __expf(mr1 - nm1);
        mr0 = nm0; mr1 = nm1;

        float rs0 = 0.f, rs1 = 0.f;
#pragma unroll
        for (int nt = 0; nt < 8; nt++) {
            c[nt][0] = __expf(c[nt][0] - nm0);
            c[nt][1] = __expf(c[nt][1] - nm0);
            c[nt][2] = __expf(c[nt][2] - nm1);
            c[nt][3] = __expf(c[nt][3] - nm1);
            rs0 += c[nt][0] + c[nt][1];
            rs1 += c[nt][2] + c[nt][3];
        }
        rs0 += __shfl_xor_sync(0xffffffffu, rs0, 1);
        rs0 += __shfl_xor_sync(0xffffffffu, rs0, 2);
        rs1 += __shfl_xor_sync(0xffffffffu, rs1, 1);
        rs1 += __shfl_xor_sync(0xffffffffu, rs1, 2);
        lr0 = lr0 * corr0 + rs0;
        lr1 = lr1 * corr1 + rs1;

#pragma unroll
        for (int nt = 0; nt < 8; nt++) {
            o[nt][0] *= corr0; o[nt][1] *= corr0;
            o[nt][2] *= corr1; o[nt][3] *= corr1;
        }

        // ---- P to smem (warp-private rows) ----
#pragma unroll
        for (int nt = 0; nt < 8; nt++) {
            *(float2*)&Ps[(wr0+grp)  *PS_STRIDE + nt*8 + tig*2] =
                make_float2(c[nt][0], c[nt][1]);
            *(float2*)&Ps[(wr0+grp+8)*PS_STRIDE + nt*8 + tig*2] =
                make_float2(c[nt][2], c[nt][3]);
        }
        __syncwarp();

        // ---- O += P V (compensated) ----
#pragma unroll
        for (int ks = 0; ks < 8; ks++) {
            float pv[4];
            pv[0] = Ps[(wr0+grp)  *PS_STRIDE + ks*8 + tig];
            pv[1] = Ps[(wr0+grp+8)*PS_STRIDE + ks*8 + tig];
            pv[2] = Ps[(wr0+grp)  *PS_STRIDE + ks*8 + tig + 4];
            pv[3] = Ps[(wr0+grp+8)*PS_STRIDE + ks*8 + tig + 4];
            uint32_t ahi[4], alo[4];
#pragma unroll
            for (int e = 0; e < 4; e++) {
                float hi = to_tf32(pv[e]);
                ahi[e] = __float_as_uint(hi);
                alo[e] = __float_as_uint(to_tf32(pv[e] - hi));
            }
#pragma unroll
            for (int nt = 0; nt < 8; nt++) {
                float2 v0 = Vhl[(ks*8+tig)  *KHL_STRIDE + nt*8 + grp];
                float2 v1 = Vhl[(ks*8+tig+4)*KHL_STRIDE + nt*8 + grp];
                uint32_t bhi[2] = {__float_as_uint(v0.x), __float_as_uint(v1.x)};
                uint32_t blo[2] = {__float_as_uint(v0.y), __float_as_uint(v1.y)};
                mma_tf32(o[nt], ahi, bhi);
                mma_tf32(o[nt], ahi, blo);
                mma_tf32(o[nt], alo, bhi);
            }
        }
    }

    // ---- epilogue: normalize, write [B,T,C] ----
    float i0 = 1.f / lr0, i1 = 1.f / lr1;
    float* y0 = g_att + ((size_t)(b*TT + q0 + wr0 + grp))*CC + h*DD;
    float* y1 = g_att + ((size_t)(b*TT + q0 + wr0 + grp + 8))*CC + h*DD;
#pragma unroll
    for (int nt = 0; nt < 8; nt++) {
        *(float2*)(y0 + nt*8 + tig*2) = make_float2(o[nt][0]*i0, o[nt][1]*i0);
        *(float2*)(y1 + nt*8 + tig*2) = make_float2(o[nt][2]*i1, o[nt][3]*i1);
    }
}

// ---------------------------------------------------------------------------
extern "C" void kernel_launch(void* const* d_in, const int* in_sizes, int n_in,
                              void* d_out, int out_size)
{
    const float* x  = (const float*)d_in[0];
    const float* Wq = (const float*)d_in[1];
    const float* bq = (const float*)d_in[2];
    const float* Wk = (const float*)d_in[3];
    const float* bk = (const float*)d_in[4];
    const float* Wv = (const float*)d_in[5];
    const float* bv = (const float*)d_in[6];
    const float* Wp = (const float*)d_in[7];
    const float* bp = (const float*)d_in[8];
    float* out = (float*)d_out;

    cudaFuncSetAttribute(attn_kernel,
                         cudaFuncAttributeMaxDynamicSharedMemorySize,
                         ATT_SMEM_BYTES);

    // 1. QKV projections (tf32 mma.sync)
    dim3 qkv_grid(GN/128, MM/128, 3);   // (8, 32, 3)
    mm_qkv_kernel<<<qkv_grid, 256>>>(x, Wq, bq, Wk, bk, Wv, bv);

    // 2. RoPE
    int rope_threads = 2 * NPAIR;
    rope_kernel<<<(rope_threads + 255) / 256, 256>>>();

    // 3. Tensor-core causal flash attention
    dim3 attn_grid(TT/128, BB*HH);      // (16, 32)
    attn_kernel<<<attn_grid, 256, ATT_SMEM_BYTES>>>();

    // 4. Output projection (tf32 mma.sync)
    dim3 proj_grid(GN/128, MM/128);
    mm_proj_kernel<<<proj_grid, 256>>>(Wp, bp, out);
}

// round 8
// speedup vs baseline: 2.2590x; 1.0330x over previous
#include <cuda_runtime.h>
#include <math.h>
#include <stdint.h>

// Problem constants
#define BB 2
#define TT 2048
#define HH 16
#define DD 64
#define CC 1024
#define MM (BB*TT)   // 4096

// Scratch (allocation-free rule: __device__ globals)
__device__ float g_q[MM*CC];
__device__ float g_k[MM*CC];
__device__ float g_v[MM*CC];
__device__ float g_att[MM*CC];
// interleaved (hi,lo) tf32 splits of rope'd K and raw V: [B,T,H,D*2]
__device__ float g_khl[MM*CC*2];
__device__ float g_vhl[MM*CC*2];

// ---------------------------------------------------------------------------
// tf32 helpers
// ---------------------------------------------------------------------------
__device__ __forceinline__ float to_tf32(float x) {
    float r;
    asm("cvt.rna.tf32.f32 %0, %1;" : "=f"(r) : "f"(x));
    return r;
}

__device__ __forceinline__ void mma_tf32(float c[4], const uint32_t a[4],
                                         const uint32_t b[2])
{
    asm volatile(
        "mma.sync.aligned.m16n8k8.row.col.f32.tf32.tf32.f32 "
        "{%0,%1,%2,%3}, {%4,%5,%6,%7}, {%8,%9}, {%0,%1,%2,%3};"
        : "+f"(c[0]), "+f"(c[1]), "+f"(c[2]), "+f"(c[3])
        : "r"(a[0]), "r"(a[1]), "r"(a[2]), "r"(a[3]),
          "r"(b[0]), "r"(b[1]));
}

__device__ __forceinline__ uint32_t smem_u32(const void* p) {
    uint32_t a;
    asm("{ .reg .u64 t; cvta.to.shared.u64 t, %1; cvt.u32.u64 %0, t; }"
        : "=r"(a) : "l"(p));
    return a;
}

// ===========================================================================
// tf32 mma.sync GEMM (unchanged — confirmed 105us each)
// ===========================================================================
#define GK 1024
#define GN 1024
#define BKt 16
#define SPAD 132

__device__ __forceinline__ void mm128_body(
    const float* __restrict__ A, const float* __restrict__ W,
    const float* __restrict__ bias, float* __restrict__ out)
{
    __shared__ float As[2][BKt][SPAD];
    __shared__ float Bs[2][BKt][SPAD];

    int tid = threadIdx.x;
    int wid = tid >> 5;
    int lane = tid & 31;
    int grp = lane >> 2;
    int tig = lane & 3;
    int wm = wid >> 1;
    int wn = wid & 1;

    int m0 = blockIdx.y * 128;
    int n0 = blockIdx.x * 128;

    int r0 = tid >> 2;
    int c40 = (tid & 3) * 4;

    const float* Ag0 = A + (size_t)(m0 + r0) * GK + c40;
    const float* Ag1 = A + (size_t)(m0 + r0 + 64) * GK + c40;
    const float* Wg0 = W + (size_t)(n0 + r0) * GK + c40;
    const float* Wg1 = W + (size_t)(n0 + r0 + 64) * GK + c40;

    float c[2][8][4];
#pragma unroll
    for (int mt = 0; mt < 2; mt++)
#pragma unroll
        for (int nt = 0; nt < 8; nt++)
#pragma unroll
            for (int i = 0; i < 4; i++) c[mt][nt][i] = 0.f;

    float4 a0 = *(const float4*)(Ag0);
    float4 a1 = *(const float4*)(Ag1);
    float4 w0 = *(const float4*)(Wg0);
    float4 w1 = *(const float4*)(Wg1);

#define STORE_TILE(buf)                                                     \
    do {                                                                    \
        As[buf][c40+0][r0]    = to_tf32(a0.x);                              \
        As[buf][c40+1][r0]    = to_tf32(a0.y);                              \
        As[buf][c40+2][r0]    = to_tf32(a0.z);                              \
        As[buf][c40+3][r0]    = to_tf32(a0.w);                              \
        As[buf][c40+0][r0+64] = to_tf32(a1.x);                              \
        As[buf][c40+1][r0+64] = to_tf32(a1.y);                              \
        As[buf][c40+2][r0+64] = to_tf32(a1.z);                              \
        As[buf][c40+3][r0+64] = to_tf32(a1.w);                              \
        Bs[buf][c40+0][r0]    = to_tf32(w0.x);                              \
        Bs[buf][c40+1][r0]    = to_tf32(w0.y);                              \
        Bs[buf][c40+2][r0]    = to_tf32(w0.z);                              \
        Bs[buf][c40+3][r0]    = to_tf32(w0.w);                              \
        Bs[buf][c40+0][r0+64] = to_tf32(w1.x);                              \
        Bs[buf][c40+1][r0+64] = to_tf32(w1.y);                              \
        Bs[buf][c40+2][r0+64] = to_tf32(w1.z);                              \
        Bs[buf][c40+3][r0+64] = to_tf32(w1.w);                              \
    } while (0)

#define COMPUTE_TILE(buf)                                                   \
    do {                                                                    \
        _Pragma("unroll")                                                   \
        for (int ks = 0; ks < 2; ks++) {                                    \
            int kk = ks * 8;                                                \
            uint32_t afr[2][4];                                             \
            _Pragma("unroll")                                               \
            for (int mt = 0; mt < 2; mt++) {                                \
                int rm = wm*32 + mt*16;                                     \
                afr[mt][0] = __float_as_uint(As[buf][kk+tig][rm+grp]);      \
                afr[mt][1] = __float_as_uint(As[buf][kk+tig][rm+grp+8]);    \
                afr[mt][2] = __float_as_uint(As[buf][kk+tig+4][rm+grp]);    \
                afr[mt][3] = __float_as_uint(As[buf][kk+tig+4][rm+grp+8]);  \
            }                                                               \
            uint32_t bfr[8][2];                                             \
            _Pragma("unroll")                                               \
            for (int nt = 0; nt < 8; nt++) {                                \
                int cn = wn*64 + nt*8;                                      \
                bfr[nt][0] = __float_as_uint(Bs[buf][kk+tig][cn+grp]);      \
                bfr[nt][1] = __float_as_uint(Bs[buf][kk+tig+4][cn+grp]);    \
            }                                                               \
            _Pragma("unroll")                                               \
            for (int mt = 0; mt < 2; mt++)                                  \
                _Pragma("unroll")                                           \
                for (int nt = 0; nt < 8; nt++)                              \
                    mma_tf32(c[mt][nt], afr[mt], bfr[nt]);                  \
        }                                                                   \
    } while (0)

    STORE_TILE(0);
    __syncthreads();

    const int NT = GK / BKt;
    for (int it = 1; it < NT; it++) {
        int k0 = it * BKt;
        a0 = *(const float4*)(Ag0 + k0);
        a1 = *(const float4*)(Ag1 + k0);
        w0 = *(const float4*)(Wg0 + k0);
        w1 = *(const float4*)(Wg1 + k0);

        int buf = (it - 1) & 1;
        COMPUTE_TILE(buf);

        int nb = it & 1;
        __syncthreads();
        STORE_TILE(nb);
        __syncthreads();
    }
    COMPUTE_TILE((NT - 1) & 1);

#undef STORE_TILE
#undef COMPUTE_TILE

#pragma unroll
    for (int mt = 0; mt < 2; mt++) {
        int row = m0 + wm*32 + mt*16 + grp;
#pragma unroll
        for (int nt = 0; nt < 8; nt++) {
            int col = n0 + wn*64 + nt*8 + tig*2;
            float2 bv = *(const float2*)(bias + col);
            float2 o0, o1;
            o0.x = c[mt][nt][0] + bv.x;
            o0.y = c[mt][nt][1] + bv.y;
            o1.x = c[mt][nt][2] + bv.x;
            o1.y = c[mt][nt][3] + bv.y;
            *(float2*)(out + (size_t)row * GN + col) = o0;
            *(float2*)(out + (size_t)(row + 8) * GN + col) = o1;
        }
    }
}

__global__ __launch_bounds__(256)
void mm_qkv_kernel(const float* __restrict__ x,
                   const float* __restrict__ Wq, const float* __restrict__ bq,
                   const float* __restrict__ Wk, const float* __restrict__ bk,
                   const float* __restrict__ Wv, const float* __restrict__ bv)
{
    const float* W; const float* b; float* out;
    if (blockIdx.z == 0)      { W = Wq; b = bq; out = g_q; }
    else if (blockIdx.z == 1) { W = Wk; b = bk; out = g_k; }
    else                      { W = Wv; b = bv; out = g_v; }
    mm128_body(x, W, b, out);
}

__global__ __launch_bounds__(256)
void mm_proj_kernel(const float* __restrict__ Wp, const float* __restrict__ bp,
                    float* __restrict__ out)
{
    mm128_body(g_att, Wp, bp, out);
}

// ---------------------------------------------------------------------------
// RoPE + hi/lo split. Segment 0: q rope in place. Segment 1: k rope ->
// g_khl interleaved (hi,lo). Segment 2: v split -> g_vhl.
// ---------------------------------------------------------------------------
#define NPAIR (BB*TT*HH*32)

__device__ __forceinline__ void split_store(float* dst, float v) {
    float hi = to_tf32(v);
    dst[0] = hi;
    dst[1] = to_tf32(v - hi);
}

__global__ __launch_bounds__(256)
void rope_split_kernel()
{
    int idx = blockIdx.x * blockDim.x + threadIdx.x;
    if (idx >= 3 * NPAIR) return;
    int seg = idx / NPAIR;          // 0: q, 1: k, 2: v
    int i = idx - seg * NPAIR;
    int j = i & 31;
    int h = (i >> 5) & 15;
    int t = (i >> 9) & 2047;
    int b = i >> 20;
    size_t base = (((size_t)(b*TT + t))*HH + h) * DD;

    if (seg == 2) {
        float v1 = g_v[base + j];
        float v2 = g_v[base + j + 32];
        split_store(g_vhl + base*2 + 2*j, v1);
        split_store(g_vhl + base*2 + 2*(j+32), v2);
        return;
    }

    const float L = 13.287712379549449f / 32.0f;  // log2(10000)/32
    float inv = exp2f(-(float)j * L);
    float ang = (float)t * inv;
    float c, s;
    sincosf(ang, &s, &c);

    if (seg == 0) {
        float* p = g_q + base;
        float x1 = p[j], x2 = p[j + 32];
        p[j]      = x1 * c - x2 * s;
        p[j + 32] = x2 * c + x1 * s;
    } else {
        const float* p = g_k + base;
        float x1 = p[j], x2 = p[j + 32];
        float r1 = x1 * c - x2 * s;
        float r2 = x2 * c + x1 * s;
        split_store(g_khl + base*2 + 2*j, r1);
        split_store(g_khl + base*2 + 2*(j+32), r2);
    }
}

// ===========================================================================
// Tensor-core causal flash attention, tf32 mma with hi/lo compensation.
// K/V hi-lo pairs pre-split in global; tiles streamed via cp.async with
// 2-buffer pipeline. Fragment layout identical to R7 (verified).
// ===========================================================================
#define KHL_STRIDE 68   // float2 units per row
#define PS_STRIDE 72
#define KBUF_BYTES (64 * KHL_STRIDE * 8)               // 34816
#define ATT_SMEM_BYTES (4*KBUF_BYTES + 128*PS_STRIDE*4)  // 176128

__global__ __launch_bounds__(256)
void attn_kernel()
{
    extern __shared__ float smf[];
    // [Khl buf0][Khl buf1][Vhl buf0][Vhl buf1][Ps]
    float2* KhlB = (float2*)smf;
    float2* VhlB = KhlB + 2 * 64 * KHL_STRIDE;
    float*  Ps   = (float*)(VhlB + 2 * 64 * KHL_STRIDE);
    const uint32_t khl_s0 = smem_u32(KhlB);
    const uint32_t vhl_s0 = khl_s0 + 2 * KBUF_BYTES;

    const int tid = threadIdx.x;
    const int lane = tid & 31, wid = tid >> 5;
    const int grp = lane >> 2, tig = lane & 3;
    const int qtile = gridDim.x - 1 - blockIdx.x;   // big work first
    const int bh = blockIdx.y;
    const int b = bh >> 4, h = bh & 15;
    const int q0 = qtile * 128;
    const int wr0 = wid * 16;

    // loader mapping for cp.async: 2048 16B-chunks per array, 8 per thread
    const int lr = tid >> 2;          // base row pattern
    // (recomputed inside macro per chunk)

    // ---- issue one K/V tile (64 rows x 128 floats interleaved) ----
#define ISSUE_TILE(kt_, buf_)                                               \
    do {                                                                    \
        int k0_ = (kt_) * 64;                                               \
        size_t gbase_ = (((size_t)(b*TT + k0_))*HH + h) * (size_t)(DD*2);   \
        const float* kg_ = g_khl + gbase_;                                  \
        const float* vg_ = g_vhl + gbase_;                                  \
        uint32_t kd_ = khl_s0 + (buf_) * KBUF_BYTES;                        \
        uint32_t vd_ = vhl_s0 + (buf_) * KBUF_BYTES;                        \
        _Pragma("unroll")                                                   \
        for (int j_ = 0; j_ < 8; j_++) {                                    \
            int idx_ = tid + 256 * j_;        /* 0..2047 */                 \
            int r_ = idx_ >> 5;               /* 0..63 */                   \
            int cc_ = idx_ & 31;              /* 16B chunk */               \
            const float* ks_ = kg_ + (size_t)r_ * (HH*DD*2) + cc_*4;        \
            const float* vs_ = vg_ + (size_t)r_ * (HH*DD*2) + cc_*4;        \
            uint32_t kdst_ = kd_ + r_ * (KHL_STRIDE*8) + cc_*16;            \
            uint32_t vdst_ = vd_ + r_ * (KHL_STRIDE*8) + cc_*16;            \
            asm volatile("cp.async.cg.shared.global [%0], [%1], 16;"        \
                         :: "r"(kdst_), "l"(ks_) : "memory");               \
            asm volatile("cp.async.cg.shared.global [%0], [%1], 16;"        \
                         :: "r"(vdst_), "l"(vs_) : "memory");               \
        }                                                                   \
    } while (0)

    // ---- stage Q (128 rows x 64) into Ps, then build hi/lo fragments ----
    const float* qbase = g_q + (((size_t)(b*TT + q0))*HH + h) * DD;
#pragma unroll
    for (int j = 0; j < 8; j++) {
        int idx = tid + 256*j;
        int r = idx >> 4, c4 = idx & 15;
        float4 v = ((const float4*)(qbase + (size_t)r * (HH*DD)))[c4];
        *(float4*)&Ps[r*PS_STRIDE + c4*4] = v;
    }

    // prologue: tile 0 -> buf 0 (overlaps with Q fragment extraction)
    ISSUE_TILE(0, 0);
    asm volatile("cp.async.commit_group;" ::: "memory");

    __syncthreads();

    uint32_t qhi[8][4], qlo[8][4];
#pragma unroll
    for (int ks = 0; ks < 8; ks++) {
        float qv[4];
        qv[0] = Ps[(wr0+grp)  *PS_STRIDE + ks*8 + tig];
        qv[1] = Ps[(wr0+grp+8)*PS_STRIDE + ks*8 + tig];
        qv[2] = Ps[(wr0+grp)  *PS_STRIDE + ks*8 + tig + 4];
        qv[3] = Ps[(wr0+grp+8)*PS_STRIDE + ks*8 + tig + 4];
#pragma unroll
        for (int e = 0; e < 4; e++) {
            float hi = to_tf32(qv[e]);
            qhi[ks][e] = __float_as_uint(hi);
            qlo[ks][e] = __float_as_uint(to_tf32(qv[e] - hi));
        }
    }

    float o[8][4];
#pragma unroll
    for (int nt = 0; nt < 8; nt++)
#pragma unroll
        for (int e = 0; e < 4; e++) o[nt][e] = 0.f;
    float mr0 = -1e30f, mr1 = -1e30f, lr0v = 0.f, lr1v = 0.f;

    const int row0 = q0 + wr0 + grp;
    const int row1 = row0 + 8;
    const int ntiles = 2*qtile + 2;

    for (int kt = 0; kt < ntiles; kt++) {
        int buf = kt & 1;
        int k0 = kt * 64;

        // stream next tile into the other buffer
        if (kt + 1 < ntiles) ISSUE_TILE(kt + 1, buf ^ 1);
        asm volatile("cp.async.commit_group;" ::: "memory");
        asm volatile("cp.async.wait_group 1;" ::: "memory");
        __syncthreads();   // tile kt visible to all; prev compute done

        if (k0 <= q0 + wr0 + 15) {
            const float2* Khl = KhlB + buf * 64 * KHL_STRIDE;
            const float2* Vhl = VhlB + buf * 64 * KHL_STRIDE;

            // ---- S = Q K^T (compensated) ----
            float c[8][4];
#pragma unroll
            for (int nt = 0; nt < 8; nt++)
#pragma unroll
                for (int e = 0; e < 4; e++) c[nt][e] = 0.f;

#pragma unroll
            for (int ks = 0; ks < 8; ks++) {
#pragma unroll
                for (int nt = 0; nt < 8; nt++) {
                    float2 k0v = Khl[(nt*8+grp)*KHL_STRIDE + ks*8 + tig];
                    float2 k1v = Khl[(nt*8+grp)*KHL_STRIDE + ks*8 + tig + 4];
                    uint32_t bhi[2] = {__float_as_uint(k0v.x), __float_as_uint(k1v.x)};
                    uint32_t blo[2] = {__float_as_uint(k0v.y), __float_as_uint(k1v.y)};
                    mma_tf32(c[nt], qhi[ks], bhi);
                    mma_tf32(c[nt], qhi[ks], blo);
                    mma_tf32(c[nt], qlo[ks], bhi);
                }
            }

            // ---- scale + causal mask ----
#pragma unroll
            for (int nt = 0; nt < 8; nt++) {
                int col = k0 + nt*8 + tig*2;
                c[nt][0] = (col     <= row0) ? c[nt][0] * 0.125f : -1e30f;
                c[nt][1] = (col + 1 <= row0) ? c[nt][1] * 0.125f : -1e30f;
                c[nt][2] = (col     <= row1) ? c[nt][2] * 0.125f : -1e30f;
                c[nt][3] = (col + 1 <= row1) ? c[nt][3] * 0.125f : -1e30f;
            }

            // ---- online softmax (rows in 4-lane quads) ----
            float mx0 = -1e30f, mx1 = -1e30f;
#pragma unroll
            for (int nt = 0; nt < 8; nt++) {
                mx0 = fmaxf(mx0, fmaxf(c[nt][0], c[nt][1]));
                mx1 = fmaxf(mx1, fmaxf(c[nt][2], c[nt][3]));
            }
            mx0 = fmaxf(mx0, __shfl_xor_sync(0xffffffffu, mx0, 1));
            mx0 = fmaxf(mx0, __shfl_xor_sync(0xffffffffu, mx0, 2));
            mx1 = fmaxf(mx1, __shfl_xor_sync(0xffffffffu, mx1, 1));
            mx1 = fmaxf(mx1, __shfl_xor_sync(0xffffffffu, mx1, 2));

            float nm0 = fmaxf(mr0, mx0), nm1 = fmaxf(mr1, mx1);
            float corr0 = __expf(mr0 - nm0), corr1 = __expf(mr1 - nm1);
            mr0 = nm0; mr1 = nm1;

            float rs0 = 0.f, rs1 = 0.f;
#pragma unroll
            for (int nt = 0; nt < 8; nt++) {
                c[nt][0] = __expf(c[nt][0] - nm0);
                c[nt][1] = __expf(c[nt][1] - nm0);
                c[nt][2] = __expf(c[nt][2] - nm1);
                c[nt][3] = __expf(c[nt][3] - nm1);
                rs0 += c[nt][0] + c[nt][1];
                rs1 += c[nt][2] + c[nt][3];
            }
            rs0 += __shfl_xor_sync(0xffffffffu, rs0, 1);
            rs0 += __shfl_xor_sync(0xffffffffu, rs0, 2);
            rs1 += __shfl_xor_sync(0xffffffffu, rs1, 1);
            rs1 += __shfl_xor_sync(0xffffffffu, rs1, 2);
            lr0v = lr0v * corr0 + rs0;
            lr1v = lr1v * corr1 + rs1;

#pragma unroll
            for (int nt = 0; nt < 8; nt++) {
                o[nt][0] *= corr0; o[nt][1] *= corr0;
                o[nt][2] *= corr1; o[nt][3] *= corr1;
            }

            // ---- P to smem (warp-private rows) ----
#pragma unroll
            for (int nt = 0; nt < 8; nt++) {
                *(float2*)&Ps[(wr0+grp)  *PS_STRIDE + nt*8 + tig*2] =
                    make_float2(c[nt][0], c[nt][1]);
                *(float2*)&Ps[(wr0+grp+8)*PS_STRIDE + nt*8 + tig*2] =
                    make_float2(c[nt][2], c[nt][3]);
            }
            __syncwarp();

            // ---- O += P V (compensated) ----
#pragma unroll
            for (int ks = 0; ks < 8; ks++) {
                float pv[4];
                pv[0] = Ps[(wr0+grp)  *PS_STRIDE + ks*8 + tig];
                pv[1] = Ps[(wr0+grp+8)*PS_STRIDE + ks*8 + tig];
                pv[2] = Ps[(wr0+grp)  *PS_STRIDE + ks*8 + tig + 4];
                pv[3] = Ps[(wr0+grp+8)*PS_STRIDE + ks*8 + tig + 4];
                uint32_t ahi[4], alo[4];
#pragma unroll
                for (int e = 0; e < 4; e++) {
                    float hi = to_tf32(pv[e]);
                    ahi[e] = __float_as_uint(hi);
                    alo[e] = __float_as_uint(to_tf32(pv[e] - hi));
                }
#pragma unroll
                for (int nt = 0; nt < 8; nt++) {
                    float2 v0 = Vhl[(ks*8+tig)  *KHL_STRIDE + nt*8 + grp];
                    float2 v1 = Vhl[(ks*8+tig+4)*KHL_STRIDE + nt*8 + grp];
                    uint32_t bhi[2] = {__float_as_uint(v0.x), __float_as_uint(v1.x)};
                    uint32_t blo[2] = {__float_as_uint(v0.y), __float_as_uint(v1.y)};
                    mma_tf32(o[nt], ahi, bhi);
                    mma_tf32(o[nt], ahi, blo);
                    mma_tf32(o[nt], alo, bhi);
                }
            }
        }
        __syncthreads();   // all readers of buf done before it is refilled
    }
#undef ISSUE_TILE

    // ---- epilogue ----
    float i0 = 1.f / lr0v, i1 = 1.f / lr1v;
    float* y0 = g_att + ((size_t)(b*TT + q0 + wr0 + grp))*CC + h*DD;
    float* y1 = g_att + ((size_t)(b*TT + q0 + wr0 + grp + 8))*CC + h*DD;
#pragma unroll
    for (int nt = 0; nt < 8; nt++) {
        *(float2*)(y0 + nt*8 + tig*2) = make_float2(o[nt][0]*i0, o[nt][1]*i0);
        *(float2*)(y1 + nt*8 + tig*2) = make_float2(o[nt][2]*i1, o[nt][3]*i1);
    }
}

// ---------------------------------------------------------------------------
extern "C" void kernel_launch(void* const* d_in, const int* in_sizes, int n_in,
                              void* d_out, int out_size)
{
    const float* x  = (const float*)d_in[0];
    const float* Wq = (const float*)d_in[1];
    const float* bq = (const float*)d_in[2];
    const float* Wk = (const float*)d_in[3];
    const float* bk = (const float*)d_in[4];
    const float* Wv = (const float*)d_in[5];
    const float* bv = (const float*)d_in[6];
    const float* Wp = (const float*)d_in[7];
    const float* bp = (const float*)d_in[8];
    float* out = (float*)d_out;

    cudaFuncSetAttribute(attn_kernel,
                         cudaFuncAttributeMaxDynamicSharedMemorySize,
                         ATT_SMEM_BYTES);

    // 1. QKV projections (tf32 mma.sync)
    dim3 qkv_grid(GN/128, MM/128, 3);   // (8, 32, 3)
    mm_qkv_kernel<<<qkv_grid, 256>>>(x, Wq, bq, Wk, bk, Wv, bv);

    // 2. RoPE + hi/lo split of K and V
    int total = 3 * NPAIR;
    rope_split_kernel<<<(total + 255) / 256, 256>>>();

    // 3. Tensor-core causal flash attention (cp.async pipelined)
    dim3 attn_grid(TT/128, BB*HH);      // (16, 32)
    attn_kernel<<<attn_grid, 256, ATT_SMEM_BYTES>>>();

    // 4. Output projection (tf32 mma.sync)
    dim3 proj_grid(GN/128, MM/128);
    mm_proj_kernel<<<proj_grid, 256>>>(Wp, bp, out);
}